// round 7
// baseline (speedup 1.0000x reference)
#include <cuda_runtime.h>
#include <math.h>

#define KC 8
#define GRID 444
#define NTHREADS 128

typedef unsigned long long ull;

__device__ double g_part[GRID];
__device__ unsigned int g_ctr;   // zero-init; finalizer resets to 0 each run

// ---- packed f32x2 helpers ----
__device__ __forceinline__ ull f2fma(ull a, ull b, ull c) {
    ull r; asm("fma.rn.f32x2 %0, %1, %2, %3;" : "=l"(r) : "l"(a), "l"(b), "l"(c)); return r;
}
__device__ __forceinline__ ull f2mul(ull a, ull b) {
    ull r; asm("mul.rn.f32x2 %0, %1, %2;" : "=l"(r) : "l"(a), "l"(b)); return r;
}
__device__ __forceinline__ ull pk2(float lo, float hi) {
    ull r; asm("mov.b64 %0, {%1, %2};" : "=l"(r) : "f"(lo), "f"(hi)); return r;
}
__device__ __forceinline__ void upk2(ull v, float& lo, float& hi) {
    asm("mov.b64 {%0, %1}, %2;" : "=f"(lo), "=f"(hi) : "l"(v));
}
__device__ __forceinline__ float ex2f(float x) {
    float r; asm("ex2.approx.f32 %0, %1;" : "=f"(r) : "f"(x)); return r;
}

// densities for one point, cluster-paired constants (register-resident)
__device__ __forceinline__ void point_dens(
    float4 x, const ull PA[4][10], const ull PB[4][4], const ull PC2[4],
    float d[KC])
{
    ull Xx = pk2(x.x, x.x), Xy = pk2(x.y, x.y), Xz = pk2(x.z, x.z), Xw = pk2(x.w, x.w);
    const ull NEG1 = pk2(-1.0f, -1.0f);
#pragma unroll
    for (int p = 0; p < 4; p++) {
        ull y0 = f2fma(PA[p][0], Xx, PB[p][0]);
        ull y1 = f2fma(PA[p][1], Xx, f2fma(PA[p][2], Xy, PB[p][1]));
        ull y2 = f2fma(PA[p][3], Xx, f2fma(PA[p][4], Xy, f2fma(PA[p][5], Xz, PB[p][2])));
        ull y3 = f2fma(PA[p][6], Xx, f2fma(PA[p][7], Xy, f2fma(PA[p][8], Xz, f2fma(PA[p][9], Xw, PB[p][3]))));
        ull s = f2mul(y0, y0);
        s = f2fma(y1, y1, s);
        s = f2fma(y2, y2, s);
        s = f2fma(y3, y3, s);
        ull tq = f2fma(s, NEG1, PC2[p]);   // C2 - s, packed
        float t0, t1;
        upk2(tq, t0, t1);
        d[2 * p]     = ex2f(t0);
        d[2 * p + 1] = ex2f(t1);
    }
}

// =======================================================================
// ONE fused kernel: per-block redundant setup -> main loop (2-pt unroll,
// W constants in SMEM broadcast) -> last-block finalize.
// 3 blocks/SM via launch bounds: occupancy is the lever this round.
// =======================================================================
__global__ void __launch_bounds__(NTHREADS, 3) gmm_all(
    const float4* __restrict__ X,
    const float*  __restrict__ means,
    const float*  __restrict__ chols,
    const float*  __restrict__ weights,
    float* __restrict__ out, int N)
{
    __shared__ float sA[KC][10];
    __shared__ float sB[KC][4];
    __shared__ float sC2[KC];
    __shared__ float sW[KC][KC];
    __shared__ float sWPs[36];       // packed symmetric W, stays in SMEM
    __shared__ float sSig[KC][16];
    __shared__ float red0[2], red1[2], red2[2];
    __shared__ float slogz;
    __shared__ double sred[NTHREADS / 32];
    __shared__ int s_last;

    const int t = threadIdx.x;
    const int lane = t & 31, warp = t >> 5;
    const unsigned full = 0xffffffffu;
    const float LOG2E = 1.4426950408889634f;
    const float LN2PI = 1.8378770664093454f;
    const float SCL   = 0.8493218002880191f;   // sqrt(0.5*log2(e))

    // ---------------- setup phase 1: per-cluster constants (threads 0..7) ----
    if (t < KC) {
        const int k = t;
        float L[4][4];
#pragma unroll
        for (int r = 0; r < 4; r++)
#pragma unroll
            for (int c = 0; c < 4; c++)
                L[r][c] = (c <= r) ? chols[k * 16 + r * 4 + c] : 0.0f;
        float S[4][4];
#pragma unroll
        for (int r = 0; r < 4; r++)
#pragma unroll
            for (int c = 0; c < 4; c++) {
                float s = (r == c) ? 1.0f : 0.0f;
#pragma unroll
                for (int m = 0; m < 4; m++) s = fmaf(L[r][m], L[c][m], s);
                S[r][c] = s;
                sSig[k][r * 4 + c] = s;
            }
        float M[4][4];
#pragma unroll
        for (int r = 0; r < 4; r++) {
#pragma unroll
            for (int c = 0; c < 4; c++) {
                if (c > r) { M[r][c] = 0.0f; continue; }
                float s = S[r][c];
#pragma unroll
                for (int m = 0; m < 4; m++)
                    if (m < c) s = fmaf(-M[r][m], M[c][m], s);
                if (r == c) M[r][r] = sqrtf(s);
                else        M[r][c] = s / M[c][c];
            }
        }
        float A[4][4];
#pragma unroll
        for (int r = 0; r < 4; r++) {
#pragma unroll
            for (int c = 0; c < 4; c++) A[r][c] = 0.0f;
            A[r][r] = 1.0f / M[r][r];
#pragma unroll
            for (int c = 0; c < 4; c++) {
                if (c >= r) continue;
                float s = 0.0f;
#pragma unroll
                for (int m = 0; m < 4; m++)
                    if (m >= c && m < r) s = fmaf(M[r][m], A[m][c], s);
                A[r][c] = -s * A[r][r];
            }
        }
        float logdet = 2.0f * logf(M[0][0] * M[1][1] * M[2][2] * M[3][3]);
        sC2[k] = -0.5f * (4.0f * LN2PI + logdet) * LOG2E;
        int idx = 0;
#pragma unroll
        for (int r = 0; r < 4; r++)
#pragma unroll
            for (int c = 0; c < 4; c++)
                if (c <= r) sA[k][idx++] = A[r][c] * SCL;
#pragma unroll
        for (int r = 0; r < 4; r++) {
            float b = 0.0f;
#pragma unroll
            for (int c = 0; c < 4; c++)
                if (c <= r) b = fmaf(A[r][c], means[k * 4 + c], b);
            sB[k][r] = -b * SCL;
        }
    }
    __syncthreads();

    // ---------------- setup phase 2: softmax W + z (threads 0..63) ----------
    const int i8 = t >> 3, j8 = t & 7;
    float wij = 0.0f, m = -1e30f;
    if (t < 64) {
        wij = weights[i8] * weights[j8];
        m = wij;
#pragma unroll
        for (int o = 16; o > 0; o >>= 1) m = fmaxf(m, __shfl_xor_sync(full, m, o));
        if (lane == 0) red0[warp] = m;
    }
    __syncthreads();
    float e = 0.0f;
    if (t < 64) {
        m = fmaxf(red0[0], red0[1]);
        e = __expf(wij - m);
        float s = e;
#pragma unroll
        for (int o = 16; o > 0; o >>= 1) s += __shfl_xor_sync(full, s, o);
        if (lane == 0) red1[warp] = s;
    }
    __syncthreads();
    if (t < 64) {
        float s = red1[0] + red1[1];
        float Wij = e / s;
        sW[i8][j8] = Wij;
        float Ss[4][4];
#pragma unroll
        for (int r = 0; r < 4; r++)
#pragma unroll
            for (int c = 0; c < 4; c++)
                Ss[r][c] = sSig[i8][r * 4 + c] + sSig[j8][r * 4 + c];
        float M[4][4];
#pragma unroll
        for (int r = 0; r < 4; r++) {
#pragma unroll
            for (int c = 0; c < 4; c++) {
                if (c > r) { M[r][c] = 0.0f; continue; }
                float s2 = Ss[r][c];
#pragma unroll
                for (int mm = 0; mm < 4; mm++)
                    if (mm < c) s2 = fmaf(-M[r][mm], M[c][mm], s2);
                if (r == c) M[r][r] = sqrtf(s2);
                else        M[r][c] = s2 / M[c][c];
            }
        }
        float ld = 2.0f * logf(M[0][0] * M[1][1] * M[2][2] * M[3][3]);
        float y[4];
#pragma unroll
        for (int r = 0; r < 4; r++) {
            float s2 = means[i8 * 4 + r] - means[j8 * 4 + r];
#pragma unroll
            for (int mm = 0; mm < 4; mm++)
                if (mm < r) s2 = fmaf(-M[r][mm], y[mm], s2);
            y[r] = s2 / M[r][r];
        }
        float md = y[0] * y[0] + y[1] * y[1] + y[2] * y[2] + y[3] * y[3];
        float zc = Wij * __expf(-0.5f * md - 0.5f * (4.0f * LN2PI + ld));
#pragma unroll
        for (int o = 16; o > 0; o >>= 1) zc += __shfl_xor_sync(full, zc, o);
        if (lane == 0) red2[warp] = zc;
    }
    __syncthreads();
    if (t == 0) {
        slogz = logf(red2[0] + red2[1]);
        // packed symmetric W into SMEM (diag once, off-diag doubled)
        int idx = 0;
#pragma unroll
        for (int a = 0; a < KC; a++) {
            sWPs[idx++] = sW[a][a];
#pragma unroll
            for (int b = a + 1; b < KC; b++) sWPs[idx++] = 2.0f * sW[a][b];
        }
    }
    __syncthreads();

    // ---------------- register constants: A/B/C2 only -----------------------
    ull PA[4][10], PB[4][4], PC2[4];
#pragma unroll
    for (int p = 0; p < 4; p++) {
#pragma unroll
        for (int q = 0; q < 10; q++) PA[p][q] = pk2(sA[2 * p][q], sA[2 * p + 1][q]);
#pragma unroll
        for (int q = 0; q < 4; q++)  PB[p][q] = pk2(sB[2 * p][q], sB[2 * p + 1][q]);
        PC2[p] = pk2(sC2[2 * p], sC2[2 * p + 1]);
    }

    // ---------------- main loop: 2 adjacent points per iteration -------------
    double acc = 0.0;
    const int gid = blockIdx.x * blockDim.x + t;
    const int nthr = gridDim.x * blockDim.x;
    const int step = 2 * nthr;
    int i = 2 * gid;
    for (; i + 1 < N; i += step) {
        float4 x0 = X[i];
        float4 x1 = X[i + 1];
        float d0[KC], d1[KC];
        point_dens(x0, PA, PB, PC2, d0);
        point_dens(x1, PA, PB, PC2, d1);
        // quad for both points, W broadcast from SMEM (shared loads CSE'd)
        float n0 = 0.0f, n1 = 0.0f;
        int idx = 0;
#pragma unroll
        for (int a = 0; a < KC; a++) {
            float w = sWPs[idx++];
            float h0 = w * d0[a];
            float h1 = w * d1[a];
#pragma unroll
            for (int b = a + 1; b < KC; b++) {
                w = sWPs[idx++];
                h0 = fmaf(w, d0[b], h0);
                h1 = fmaf(w, d1[b], h1);
            }
            n0 = fmaf(d0[a], h0, n0);
            n1 = fmaf(d1[a], h1, n1);
        }
        acc += (double)(n0 + n1);
    }
    // tail: at most one point
    for (; i < N; i++) {
        float4 x0 = X[i];
        float dd[KC];
        point_dens(x0, PA, PB, PC2, dd);
        float n0 = 0.0f;
        int idx = 0;
#pragma unroll
        for (int a = 0; a < KC; a++) {
            float h0 = sWPs[idx++] * dd[a];
#pragma unroll
            for (int b = a + 1; b < KC; b++) h0 = fmaf(sWPs[idx++], dd[b], h0);
            n0 = fmaf(dd[a], h0, n0);
        }
        acc += (double)n0;
    }

    // ---------------- block reduction (double) -------------------------------
#pragma unroll
    for (int o = 16; o > 0; o >>= 1) acc += __shfl_down_sync(full, acc, o);
    if (lane == 0) sred[warp] = acc;
    __syncthreads();
    if (t == 0) {
        double v = 0.0;
#pragma unroll
        for (int w2 = 0; w2 < NTHREADS / 32; w2++) v += sred[w2];
        g_part[blockIdx.x] = v;
        __threadfence();
        unsigned old = atomicAdd(&g_ctr, 1u);
        s_last = (old == gridDim.x - 1) ? 1 : 0;
    }
    __syncthreads();

    // ---------------- last block finalizes -----------------------------------
    if (s_last && warp == 0) {
        double s = 0.0;
        for (int b = lane; b < GRID; b += 32) s += g_part[b];
#pragma unroll
        for (int o = 16; o > 0; o >>= 1) s += __shfl_down_sync(full, s, o);
        if (lane == 0) {
            out[0] = (float)(-(log(s) - (double)slogz) / (double)N);
            g_ctr = 0;   // reset for next graph replay
        }
    }
}

extern "C" void kernel_launch(void* const* d_in, const int* in_sizes, int n_in,
                              void* d_out, int out_size) {
    const float* X       = (const float*)d_in[0];
    const float* means   = (const float*)d_in[1];
    const float* chols   = (const float*)d_in[2];
    const float* weights = (const float*)d_in[3];
    const int N = in_sizes[0] / 4;
    float* out = (float*)d_out;

    gmm_all<<<GRID, NTHREADS>>>((const float4*)X, means, chols, weights, out, N);
}

// round 8
// speedup vs baseline: 1.2361x; 1.2361x over previous
#include <cuda_runtime.h>
#include <math.h>

#define KC 8
#define GRID 296
#define NTHREADS 128

typedef unsigned long long ull;

__device__ double g_part[GRID];
__device__ unsigned int g_ctr;   // zero-init; finalizer resets to 0 each run

// ---- packed f32x2 helpers ----
__device__ __forceinline__ ull f2fma(ull a, ull b, ull c) {
    ull r; asm("fma.rn.f32x2 %0, %1, %2, %3;" : "=l"(r) : "l"(a), "l"(b), "l"(c)); return r;
}
__device__ __forceinline__ ull f2mul(ull a, ull b) {
    ull r; asm("mul.rn.f32x2 %0, %1, %2;" : "=l"(r) : "l"(a), "l"(b)); return r;
}
__device__ __forceinline__ ull pk2(float lo, float hi) {
    ull r; asm("mov.b64 %0, {%1, %2};" : "=l"(r) : "f"(lo), "f"(hi)); return r;
}
__device__ __forceinline__ void upk2(ull v, float& lo, float& hi) {
    asm("mov.b64 {%0, %1}, %2;" : "=f"(lo), "=f"(hi) : "l"(v));
}
__device__ __forceinline__ float ex2f(float x) {
    float r; asm("ex2.approx.f32 %0, %1;" : "=f"(r) : "f"(x)); return r;
}

// density + W-quadratic for one point (cluster-paired density, scalar quad)
__device__ __forceinline__ float point_num(
    float4 x, const ull PA[4][10], const ull PB[4][4], const ull PC2[4],
    const float WP[36])
{
    ull Xx = pk2(x.x, x.x), Xy = pk2(x.y, x.y), Xz = pk2(x.z, x.z), Xw = pk2(x.w, x.w);
    const ull NEG1 = pk2(-1.0f, -1.0f);
    float d[KC];
#pragma unroll
    for (int p = 0; p < 4; p++) {
        ull y0 = f2fma(PA[p][0], Xx, PB[p][0]);
        ull y1 = f2fma(PA[p][1], Xx, f2fma(PA[p][2], Xy, PB[p][1]));
        ull y2 = f2fma(PA[p][3], Xx, f2fma(PA[p][4], Xy, f2fma(PA[p][5], Xz, PB[p][2])));
        ull y3 = f2fma(PA[p][6], Xx, f2fma(PA[p][7], Xy, f2fma(PA[p][8], Xz, f2fma(PA[p][9], Xw, PB[p][3]))));
        ull s = f2mul(y0, y0);
        s = f2fma(y1, y1, s);
        s = f2fma(y2, y2, s);
        s = f2fma(y3, y3, s);
        ull tq = f2fma(s, NEG1, PC2[p]);   // C2 - s, packed
        float t0, t1;
        upk2(tq, t0, t1);
        d[2 * p]     = ex2f(t0);
        d[2 * p + 1] = ex2f(t1);
    }
    float num = 0.0f;
    int idx = 0;
#pragma unroll
    for (int a = 0; a < KC; a++) {
        float h = WP[idx++] * d[a];
#pragma unroll
        for (int b = a + 1; b < KC; b++) h = fmaf(WP[idx++], d[b], h);
        num = fmaf(d[a], h, num);
    }
    return num;
}

// =======================================================================
// ONE fused kernel: per-block redundant setup -> main loop (4-pt unroll,
// software-pipelined loads) -> last-block finalize.
// =======================================================================
__global__ void __launch_bounds__(NTHREADS) gmm_all(
    const float4* __restrict__ X,
    const float*  __restrict__ means,
    const float*  __restrict__ chols,
    const float*  __restrict__ weights,
    float* __restrict__ out, int N)
{
    __shared__ float sA[KC][10];
    __shared__ float sB[KC][4];
    __shared__ float sC2[KC];
    __shared__ float sW[KC][KC];
    __shared__ float sSig[KC][16];
    __shared__ float red0[2], red1[2], red2[2];
    __shared__ float slogz;
    __shared__ double sred[NTHREADS / 32];
    __shared__ int s_last;

    const int t = threadIdx.x;
    const int lane = t & 31, warp = t >> 5;
    const unsigned full = 0xffffffffu;
    const float LOG2E = 1.4426950408889634f;
    const float LN2PI = 1.8378770664093454f;
    const float SCL   = 0.8493218002880191f;   // sqrt(0.5*log2(e))

    // ---------------- setup phase 1: per-cluster constants (threads 0..7) ----
    if (t < KC) {
        const int k = t;
        float L[4][4];
#pragma unroll
        for (int r = 0; r < 4; r++)
#pragma unroll
            for (int c = 0; c < 4; c++)
                L[r][c] = (c <= r) ? chols[k * 16 + r * 4 + c] : 0.0f;
        float S[4][4];
#pragma unroll
        for (int r = 0; r < 4; r++)
#pragma unroll
            for (int c = 0; c < 4; c++) {
                float s = (r == c) ? 1.0f : 0.0f;
#pragma unroll
                for (int m = 0; m < 4; m++) s = fmaf(L[r][m], L[c][m], s);
                S[r][c] = s;
                sSig[k][r * 4 + c] = s;
            }
        float M[4][4];
#pragma unroll
        for (int r = 0; r < 4; r++) {
#pragma unroll
            for (int c = 0; c < 4; c++) {
                if (c > r) { M[r][c] = 0.0f; continue; }
                float s = S[r][c];
#pragma unroll
                for (int m = 0; m < 4; m++)
                    if (m < c) s = fmaf(-M[r][m], M[c][m], s);
                if (r == c) M[r][r] = sqrtf(s);
                else        M[r][c] = s / M[c][c];
            }
        }
        float A[4][4];
#pragma unroll
        for (int r = 0; r < 4; r++) {
#pragma unroll
            for (int c = 0; c < 4; c++) A[r][c] = 0.0f;
            A[r][r] = 1.0f / M[r][r];
#pragma unroll
            for (int c = 0; c < 4; c++) {
                if (c >= r) continue;
                float s = 0.0f;
#pragma unroll
                for (int m = 0; m < 4; m++)
                    if (m >= c && m < r) s = fmaf(M[r][m], A[m][c], s);
                A[r][c] = -s * A[r][r];
            }
        }
        float logdet = 2.0f * logf(M[0][0] * M[1][1] * M[2][2] * M[3][3]);
        sC2[k] = -0.5f * (4.0f * LN2PI + logdet) * LOG2E;
        int idx = 0;
#pragma unroll
        for (int r = 0; r < 4; r++)
#pragma unroll
            for (int c = 0; c < 4; c++)
                if (c <= r) sA[k][idx++] = A[r][c] * SCL;
#pragma unroll
        for (int r = 0; r < 4; r++) {
            float b = 0.0f;
#pragma unroll
            for (int c = 0; c < 4; c++)
                if (c <= r) b = fmaf(A[r][c], means[k * 4 + c], b);
            sB[k][r] = -b * SCL;
        }
    }
    __syncthreads();

    // ---------------- setup phase 2: softmax W + z (threads 0..63) ----------
    const int i8 = t >> 3, j8 = t & 7;
    float wij = 0.0f, m = -1e30f;
    if (t < 64) {
        wij = weights[i8] * weights[j8];
        m = wij;
#pragma unroll
        for (int o = 16; o > 0; o >>= 1) m = fmaxf(m, __shfl_xor_sync(full, m, o));
        if (lane == 0) red0[warp] = m;
    }
    __syncthreads();
    float e = 0.0f;
    if (t < 64) {
        m = fmaxf(red0[0], red0[1]);
        e = __expf(wij - m);
        float s = e;
#pragma unroll
        for (int o = 16; o > 0; o >>= 1) s += __shfl_xor_sync(full, s, o);
        if (lane == 0) red1[warp] = s;
    }
    __syncthreads();
    if (t < 64) {
        float s = red1[0] + red1[1];
        float Wij = e / s;
        sW[i8][j8] = Wij;
        float Ss[4][4];
#pragma unroll
        for (int r = 0; r < 4; r++)
#pragma unroll
            for (int c = 0; c < 4; c++)
                Ss[r][c] = sSig[i8][r * 4 + c] + sSig[j8][r * 4 + c];
        float M[4][4];
#pragma unroll
        for (int r = 0; r < 4; r++) {
#pragma unroll
            for (int c = 0; c < 4; c++) {
                if (c > r) { M[r][c] = 0.0f; continue; }
                float s2 = Ss[r][c];
#pragma unroll
                for (int mm = 0; mm < 4; mm++)
                    if (mm < c) s2 = fmaf(-M[r][mm], M[c][mm], s2);
                if (r == c) M[r][r] = sqrtf(s2);
                else        M[r][c] = s2 / M[c][c];
            }
        }
        float ld = 2.0f * logf(M[0][0] * M[1][1] * M[2][2] * M[3][3]);
        float y[4];
#pragma unroll
        for (int r = 0; r < 4; r++) {
            float s2 = means[i8 * 4 + r] - means[j8 * 4 + r];
#pragma unroll
            for (int mm = 0; mm < 4; mm++)
                if (mm < r) s2 = fmaf(-M[r][mm], y[mm], s2);
            y[r] = s2 / M[r][r];
        }
        float md = y[0] * y[0] + y[1] * y[1] + y[2] * y[2] + y[3] * y[3];
        float zc = Wij * __expf(-0.5f * md - 0.5f * (4.0f * LN2PI + ld));
#pragma unroll
        for (int o = 16; o > 0; o >>= 1) zc += __shfl_xor_sync(full, zc, o);
        if (lane == 0) red2[warp] = zc;
    }
    __syncthreads();
    if (t == 0) slogz = logf(red2[0] + red2[1]);
    __syncthreads();

    // ---------------- load + pack constants into registers -------------------
    ull PA[4][10], PB[4][4], PC2[4];
    float WP[36];
#pragma unroll
    for (int p = 0; p < 4; p++) {
#pragma unroll
        for (int q = 0; q < 10; q++) PA[p][q] = pk2(sA[2 * p][q], sA[2 * p + 1][q]);
#pragma unroll
        for (int q = 0; q < 4; q++)  PB[p][q] = pk2(sB[2 * p][q], sB[2 * p + 1][q]);
        PC2[p] = pk2(sC2[2 * p], sC2[2 * p + 1]);
    }
    {
        int idx = 0;
#pragma unroll
        for (int a = 0; a < KC; a++) {
            WP[idx++] = sW[a][a];
#pragma unroll
            for (int b = a + 1; b < KC; b++) WP[idx++] = 2.0f * sW[a][b];
        }
    }

    // ---------------- main loop: 4 points, software-pipelined loads ----------
    double acc = 0.0;
    const int gid = blockIdx.x * blockDim.x + t;
    const int nthr = gridDim.x * blockDim.x;
    const int step = 4 * nthr;
    int i = 4 * gid;

    float4 xa, xb, xc, xd;
    bool have = (i + 3 < N);
    if (have) {
        xa = X[i]; xb = X[i + 1]; xc = X[i + 2]; xd = X[i + 3];
    }
    while (have) {
        const int inext = i + step;
        const bool havenext = (inext + 3 < N);
        float4 ya, yb, yc, yd;
        if (havenext) {            // prefetch next group BEFORE computing
            ya = X[inext]; yb = X[inext + 1]; yc = X[inext + 2]; yd = X[inext + 3];
        }
        float n0 = point_num(xa, PA, PB, PC2, WP);
        float n1 = point_num(xb, PA, PB, PC2, WP);
        float n2 = point_num(xc, PA, PB, PC2, WP);
        float n3 = point_num(xd, PA, PB, PC2, WP);
        acc += (double)((n0 + n1) + (n2 + n3));
        xa = ya; xb = yb; xc = yc; xd = yd;
        i = inext;
        have = havenext;
    }
    // tail: at most the one straddling group
    for (; i < N; i++)
        acc += (double)point_num(X[i], PA, PB, PC2, WP);

    // ---------------- block reduction (double) -------------------------------
#pragma unroll
    for (int o = 16; o > 0; o >>= 1) acc += __shfl_down_sync(full, acc, o);
    if (lane == 0) sred[warp] = acc;
    __syncthreads();
    if (t == 0) {
        double v = 0.0;
#pragma unroll
        for (int w2 = 0; w2 < NTHREADS / 32; w2++) v += sred[w2];
        g_part[blockIdx.x] = v;
        __threadfence();
        unsigned old = atomicAdd(&g_ctr, 1u);
        s_last = (old == gridDim.x - 1) ? 1 : 0;
    }
    __syncthreads();

    // ---------------- last block finalizes -----------------------------------
    if (s_last && warp == 0) {
        double s = 0.0;
        for (int b = lane; b < GRID; b += 32) s += g_part[b];
#pragma unroll
        for (int o = 16; o > 0; o >>= 1) s += __shfl_down_sync(full, s, o);
        if (lane == 0) {
            out[0] = (float)(-(log(s) - (double)slogz) / (double)N);
            g_ctr = 0;   // reset for next graph replay
        }
    }
}

extern "C" void kernel_launch(void* const* d_in, const int* in_sizes, int n_in,
                              void* d_out, int out_size) {
    const float* X       = (const float*)d_in[0];
    const float* means   = (const float*)d_in[1];
    const float* chols   = (const float*)d_in[2];
    const float* weights = (const float*)d_in[3];
    const int N = in_sizes[0] / 4;
    float* out = (float*)d_out;

    gmm_all<<<GRID, NTHREADS>>>((const float4*)X, means, chols, weights, out, N);
}